// round 2
// baseline (speedup 1.0000x reference)
#include <cuda_runtime.h>
#include <cuda_bf16.h>
#include <math.h>

// Loss = 1.0*n2v + 0.2*wav + 0.01*tv over pred/noisy (64,1,512,512) f32, mask bool.
// Identity: |c - soft_threshold(c, thr)| == min(|c|, thr).
// Mask dtype is layout-detected at runtime (1-byte bool vs 4-byte int32/float32);
// for 4-byte encodings, (word != 0) is truth for both int32 and float32.

#define B_   64
#define H_   512
#define W_   512
#define TILE 64

#define THR1 (50.0f / 255.0f)   // 64x64 coeffs,  weight 1
#define THR2 (25.0f / 255.0f)   // 128x128 coeffs, weight 1/2
#define THR3 (12.5f / 255.0f)   // 256x256 coeffs, weight 1/3

// [0]=n2v_num [1]=mask_sum [2]=wav64 [3]=wav128 [4]=wav256 [5]=tv
__device__ double g_acc[6];
__device__ int    g_mask_is_byte;

__global__ void init_acc() {
    if (threadIdx.x < 6) g_acc[threadIdx.x] = 0.0;
    if (threadIdx.x == 6) g_mask_is_byte = 0;
}

// Scan first 4MB of mask buffer as u32 words. Packed 1-byte bools (2% ones)
// are guaranteed to produce words outside {0, 1, 0x3F800000}; int32/f32 never do.
__global__ void detect_mask_layout(const unsigned int* __restrict__ mw) {
    const int nwords = 1 << 20;  // 4 MB, in-bounds for all candidate layouts
    int found = 0;
    for (int i = blockIdx.x * blockDim.x + threadIdx.x; i < nwords;
         i += gridDim.x * blockDim.x) {
        unsigned int w = mw[i];
        if (w != 0u && w != 1u && w != 0x3F800000u) found = 1;
    }
    if (__syncthreads_or(found) && threadIdx.x == 0)
        atomicOr(&g_mask_is_byte, 1);
}

__device__ __forceinline__ float warp_sum(float v) {
    #pragma unroll
    for (int o = 16; o > 0; o >>= 1) v += __shfl_down_sync(0xFFFFFFFFu, v, o);
    return v;
}

__global__ __launch_bounds__(256)
void loss_kernel(const float* __restrict__ pred,
                 const float* __restrict__ noisy,
                 const unsigned char* __restrict__ mask8,
                 const unsigned int* __restrict__ mask32) {
    __shared__ float sm[65 * 66];      // clipped tile + TV halo, padded stride
    __shared__ float ll1[32 * 33];
    __shared__ float ll2[16 * 17];
    __shared__ float red[6][8];

    const int tid = threadIdx.x;
    const int b   = blockIdx.z;
    const int r0  = blockIdx.y * TILE;
    const int c0  = blockIdx.x * TILE;
    const size_t img_off = (size_t)b * H_ * W_;
    const float* pb = pred + img_off;
    const int mask_is_byte = g_mask_is_byte;

    // ---- load 65x65 clipped tile (halo for TV) ----
    for (int idx = tid; idx < 65 * 65; idx += 256) {
        int lr = idx / 65, lc = idx - lr * 65;
        int gr = r0 + lr, gc = c0 + lc;
        float v = 0.0f;
        if (gr < H_ && gc < W_)
            v = fminf(fmaxf(pb[gr * W_ + gc], 0.0f), 1.0f);
        sm[lr * 66 + lc] = v;
    }
    __syncthreads();

    float a_n2v = 0.0f, a_msk = 0.0f, a_tv = 0.0f;
    float a_w1 = 0.0f, a_w2 = 0.0f, a_w3 = 0.0f;

    // ---- n2v + mask sum + TV over interior 64x64 ----
    for (int idx = tid; idx < TILE * TILE; idx += 256) {
        int lr = idx >> 6, lc = idx & 63;
        int gr = r0 + lr, gc = c0 + lc;
        float p  = sm[lr * 66 + lc];
        size_t gi = img_off + (size_t)gr * W_ + gc;
        float nv = noisy[gi];
        float m;
        if (mask_is_byte) m = mask8[gi]  ? 1.0f : 0.0f;
        else              m = mask32[gi] ? 1.0f : 0.0f;   // covers int32 AND float32
        a_n2v += fabsf(p - nv) * m;
        a_msk += m;
        if (gr + 1 < H_) a_tv += fabsf(sm[(lr + 1) * 66 + lc] - p);
        if (gc + 1 < W_) a_tv += fabsf(sm[lr * 66 + lc + 1] - p);
    }

    // ---- Haar level 1: 64x64 -> 32x32 (256x256 global coeffs => THR3) ----
    for (int idx = tid; idx < 32 * 32; idx += 256) {
        int i = idx >> 5, j = idx & 31;
        float a = sm[(2 * i)     * 66 + 2 * j];
        float bb= sm[(2 * i)     * 66 + 2 * j + 1];
        float c = sm[(2 * i + 1) * 66 + 2 * j];
        float d = sm[(2 * i + 1) * 66 + 2 * j + 1];
        float ll = (a + bb + c + d) * 0.5f;
        float ch = (a + bb - c - d) * 0.5f;
        float cv = (a - bb + c - d) * 0.5f;
        float cd = (a - bb - c + d) * 0.5f;
        a_w3 += fminf(fabsf(ch), THR3) + fminf(fabsf(cv), THR3) + fminf(fabsf(cd), THR3);
        ll1[i * 33 + j] = ll;
    }
    __syncthreads();

    // ---- Haar level 2: 32x32 -> 16x16 (128x128 global => THR2) ----
    {
        int i = tid >> 4, j = tid & 15;
        float a = ll1[(2 * i)     * 33 + 2 * j];
        float bb= ll1[(2 * i)     * 33 + 2 * j + 1];
        float c = ll1[(2 * i + 1) * 33 + 2 * j];
        float d = ll1[(2 * i + 1) * 33 + 2 * j + 1];
        float ll = (a + bb + c + d) * 0.5f;
        float ch = (a + bb - c - d) * 0.5f;
        float cv = (a - bb + c - d) * 0.5f;
        float cd = (a - bb - c + d) * 0.5f;
        a_w2 += fminf(fabsf(ch), THR2) + fminf(fabsf(cv), THR2) + fminf(fabsf(cd), THR2);
        ll2[i * 17 + j] = ll;
    }
    __syncthreads();

    // ---- Haar level 3: 16x16 -> 8x8 (64x64 global => THR1) ----
    if (tid < 64) {
        int i = tid >> 3, j = tid & 7;
        float a = ll2[(2 * i)     * 17 + 2 * j];
        float bb= ll2[(2 * i)     * 17 + 2 * j + 1];
        float c = ll2[(2 * i + 1) * 17 + 2 * j];
        float d = ll2[(2 * i + 1) * 17 + 2 * j + 1];
        float ch = (a + bb - c - d) * 0.5f;
        float cv = (a - bb + c - d) * 0.5f;
        float cd = (a - bb - c + d) * 0.5f;
        a_w1 += fminf(fabsf(ch), THR1) + fminf(fabsf(cv), THR1) + fminf(fabsf(cd), THR1);
    }

    // ---- block reduce 6 partials ----
    float vals[6] = {a_n2v, a_msk, a_w1, a_w2, a_w3, a_tv};
    int lane = tid & 31, warp = tid >> 5;
    #pragma unroll
    for (int k = 0; k < 6; k++) {
        float s = warp_sum(vals[k]);
        if (lane == 0) red[k][warp] = s;
    }
    __syncthreads();
    if (tid == 0) {
        #pragma unroll
        for (int k = 0; k < 6; k++) {
            float s = 0.0f;
            #pragma unroll
            for (int w = 0; w < 8; w++) s += red[k][w];
            atomicAdd(&g_acc[k], (double)s);
        }
    }
}

__global__ void finalize(float* __restrict__ out) {
    double n2v = g_acc[0] / fmax(g_acc[1], 1.0);
    double wav = 1.0       * (g_acc[2] / (3.0 * B_ * 64.0  * 64.0))
               + (1.0/2.0) * (g_acc[3] / (3.0 * B_ * 128.0 * 128.0))
               + (1.0/3.0) * (g_acc[4] / (3.0 * B_ * 256.0 * 256.0));
    double tv  = g_acc[5] / ((double)B_ * 511.0 * 512.0);
    out[0] = (float)(1.0 * n2v + 0.2 * wav + 0.01 * tv);
}

extern "C" void kernel_launch(void* const* d_in, const int* in_sizes, int n_in,
                              void* d_out, int out_size) {
    const float* pred  = (const float*)d_in[0];
    const float* noisy = (const float*)d_in[1];
    const void*  mask  = d_in[2];
    float* out = (float*)d_out;

    init_acc<<<1, 32>>>();
    detect_mask_layout<<<64, 256>>>((const unsigned int*)mask);
    dim3 grid(W_ / TILE, H_ / TILE, B_);
    loss_kernel<<<grid, 256>>>(pred, noisy,
                               (const unsigned char*)mask,
                               (const unsigned int*)mask);
    finalize<<<1, 1>>>(out);
}

// round 4
// speedup vs baseline: 1.6127x; 1.6127x over previous
#include <cuda_runtime.h>
#include <cuda_bf16.h>
#include <math.h>

// Loss = 1.0*n2v + 0.2*wav + 0.01*tv over pred/noisy (64,1,512,512) f32, mask bool.
// Identity: |c - soft_threshold(c, thr)| == min(|c|, thr).
// Mask layout runtime-detected (1-byte bool vs 4-byte int/float; word!=0 is truth for both).
// Noisy is only loaded for float4 groups containing at least one masked pixel (~8%).
// NOTE: p4/n4 are pre-offset by img_off; index them with the IMAGE-LOCAL offset only.

#define B_   64
#define H_   512
#define W_   512
#define TH   64     // tile height
#define TW   128    // tile width
#define SMS  132    // smem row stride (floats); 132*4 bytes % 16 == 0

#define THR1 (50.0f / 255.0f)   // coarsest (64x64) coeffs,  weight 1
#define THR2 (25.0f / 255.0f)   // 128x128 coeffs,           weight 1/2
#define THR3 (12.5f / 255.0f)   // finest (256x256) coeffs,  weight 1/3

// [0]=n2v_num [1]=mask_sum [2]=wav64 [3]=wav128 [4]=wav256 [5]=tv
__device__ double g_acc[6];
__device__ int    g_mask_is_byte;

__global__ void init_acc() {
    if (threadIdx.x < 6) g_acc[threadIdx.x] = 0.0;
    if (threadIdx.x == 6) g_mask_is_byte = 0;
}

// Scan first 4MB of mask as u32. Packed bools (2% ones) must produce words
// outside {0,1,0x3F800000}; int32/f32 encodings never do.
__global__ void detect_mask_layout(const unsigned int* __restrict__ mw) {
    const int nwords = 1 << 20;
    int found = 0;
    for (int i = blockIdx.x * blockDim.x + threadIdx.x; i < nwords;
         i += gridDim.x * blockDim.x) {
        unsigned int w = mw[i];
        if (w != 0u && w != 1u && w != 0x3F800000u) found = 1;
    }
    if (__syncthreads_or(found) && threadIdx.x == 0)
        atomicOr(&g_mask_is_byte, 1);
}

__device__ __forceinline__ float warp_sum(float v) {
    #pragma unroll
    for (int o = 16; o > 0; o >>= 1) v += __shfl_down_sync(0xFFFFFFFFu, v, o);
    return v;
}

__device__ __forceinline__ float clipf(float x) {
    return fminf(fmaxf(x, 0.0f), 1.0f);
}

__global__ __launch_bounds__(256)
void loss_kernel(const float* __restrict__ pred,
                 const float* __restrict__ noisy,
                 const unsigned char* __restrict__ mask8,
                 const unsigned int* __restrict__ mask32) {
    __shared__ float sm [65 * SMS];   // clipped 64x128 tile + TV halo row/col
    __shared__ float ll1[32 * 68];    // level-1 LL (32x64), padded stride
    __shared__ float ll2[16 * 36];    // level-2 LL (16x32)
    __shared__ float red[6][8];

    const int tid = threadIdx.x;
    const int b   = blockIdx.z;
    const int r0  = blockIdx.y * TH;
    const int c0  = blockIdx.x * TW;
    const size_t img_off = (size_t)b * H_ * W_;
    const float4* p4 = (const float4*)(pred  + img_off);   // image-local
    const float4* n4 = (const float4*)(noisy + img_off);   // image-local
    const int mask_is_byte = g_mask_is_byte;
    const bool last_row_tile = (r0 + TH == H_);
    const bool last_col_tile = (c0 + TW == W_);

    // ---- load main 64x128 tile, clipped, float4 ----
    #pragma unroll
    for (int t = tid; t < TH * (TW / 4); t += 256) {
        int lr = t >> 5, v = t & 31;
        float4 x = __ldg(&p4[(size_t)(r0 + lr) * (W_ / 4) + (c0 >> 2) + v]);
        x.x = clipf(x.x); x.y = clipf(x.y); x.z = clipf(x.z); x.w = clipf(x.w);
        ((float4*)&sm[lr * SMS])[v] = x;
    }
    // ---- halo row (lr=64), full 128 cols ----
    if (tid < TW / 4) {
        float4 x = make_float4(0.f, 0.f, 0.f, 0.f);
        if (!last_row_tile) {
            x = __ldg(&p4[(size_t)(r0 + TH) * (W_ / 4) + (c0 >> 2) + tid]);
            x.x = clipf(x.x); x.y = clipf(x.y); x.z = clipf(x.z); x.w = clipf(x.w);
        }
        ((float4*)&sm[TH * SMS])[tid] = x;
    }
    // ---- halo col (lc=128), rows 0..63 ----
    if (tid >= 64 && tid < 128) {
        int lr = tid - 64;
        float x = 0.f;
        if (!last_col_tile)
            x = clipf(__ldg(&pred[img_off + (size_t)(r0 + lr) * W_ + c0 + TW]));
        sm[lr * SMS + TW] = x;
    }
    __syncthreads();

    float a_n2v = 0.f, a_msk = 0.f, a_tv = 0.f;
    float a_w1 = 0.f, a_w2 = 0.f, a_w3 = 0.f;

    // ---- n2v (sparse noisy gather) + mask + TV over 64x128 ----
    #pragma unroll
    for (int t = tid; t < TH * (TW / 4); t += 256) {
        int lr = t >> 5, v = t & 31;
        float4 p = ((const float4*)&sm[lr * SMS])[v];
        float4 d = ((const float4*)&sm[(lr + 1) * SMS])[v];
        float  rt = sm[lr * SMS + 4 * v + 4];
        size_t loff = (size_t)(r0 + lr) * W_ + c0 + 4 * v;  // image-local pixel offset
        size_t pix  = img_off + loff;                        // global pixel offset

        float m0, m1, m2, m3;
        bool any;
        if (mask_is_byte) {
            unsigned w = *(const unsigned*)(mask8 + pix);
            any = (w != 0u);
            m0 = (w & 0x000000FFu) ? 1.f : 0.f;
            m1 = (w & 0x0000FF00u) ? 1.f : 0.f;
            m2 = (w & 0x00FF0000u) ? 1.f : 0.f;
            m3 = (w & 0xFF000000u) ? 1.f : 0.f;
        } else {
            uint4 w = __ldg((const uint4*)(mask32 + pix));
            any = (w.x | w.y | w.z | w.w) != 0u;
            m0 = w.x ? 1.f : 0.f; m1 = w.y ? 1.f : 0.f;
            m2 = w.z ? 1.f : 0.f; m3 = w.w ? 1.f : 0.f;
        }
        a_msk += (m0 + m1) + (m2 + m3);
        if (any) {
            float4 nv = __ldg(&n4[loff >> 2]);   // n4 is pre-offset: local index!
            a_n2v += fabsf(p.x - nv.x) * m0 + fabsf(p.y - nv.y) * m1
                   + fabsf(p.z - nv.z) * m2 + fabsf(p.w - nv.w) * m3;
        }
        float hm = (last_col_tile && v == 31) ? 0.f : 1.f;
        float vm = (last_row_tile && lr == 63) ? 0.f : 1.f;
        a_tv += fabsf(p.y - p.x) + fabsf(p.z - p.y) + fabsf(p.w - p.z)
              + hm * fabsf(rt - p.w)
              + vm * (fabsf(d.x - p.x) + fabsf(d.y - p.y)
                    + fabsf(d.z - p.z) + fabsf(d.w - p.w));
    }

    // ---- Haar level 1: 64x128 -> 32x64 (finest => THR3). 2 outputs/item ----
    #pragma unroll
    for (int t = tid; t < 32 * 32; t += 256) {
        int i = t >> 5, j = t & 31;                   // j covers output cols 2j, 2j+1
        float4 tp = ((const float4*)&sm[(2 * i) * SMS])[j];
        float4 bt = ((const float4*)&sm[(2 * i + 1) * SMS])[j];
        float s0 = tp.x + tp.y, t0 = bt.x + bt.y, u0 = tp.x - tp.y, v0 = bt.x - bt.y;
        float ll0 = (s0 + t0) * 0.5f, ch0 = (s0 - t0) * 0.5f;
        float cv0 = (u0 + v0) * 0.5f, cd0 = (u0 - v0) * 0.5f;
        float s1 = tp.z + tp.w, t1 = bt.z + bt.w, u1 = tp.z - tp.w, v1 = bt.z - bt.w;
        float ll1v = (s1 + t1) * 0.5f, ch1 = (s1 - t1) * 0.5f;
        float cv1 = (u1 + v1) * 0.5f, cd1 = (u1 - v1) * 0.5f;
        a_w3 += fminf(fabsf(ch0), THR3) + fminf(fabsf(cv0), THR3) + fminf(fabsf(cd0), THR3)
              + fminf(fabsf(ch1), THR3) + fminf(fabsf(cv1), THR3) + fminf(fabsf(cd1), THR3);
        ll1[i * 68 + 2 * j]     = ll0;
        ll1[i * 68 + 2 * j + 1] = ll1v;
    }
    __syncthreads();

    // ---- Haar level 2: 32x64 -> 16x32 (THR2) ----
    {
        int i = tid >> 4, j = tid & 15;
        float4 tp = ((const float4*)&ll1[(2 * i) * 68])[j];
        float4 bt = ((const float4*)&ll1[(2 * i + 1) * 68])[j];
        float s0 = tp.x + tp.y, t0 = bt.x + bt.y, u0 = tp.x - tp.y, v0 = bt.x - bt.y;
        float ll0 = (s0 + t0) * 0.5f, ch0 = (s0 - t0) * 0.5f;
        float cv0 = (u0 + v0) * 0.5f, cd0 = (u0 - v0) * 0.5f;
        float s1 = tp.z + tp.w, t1 = bt.z + bt.w, u1 = tp.z - tp.w, v1 = bt.z - bt.w;
        float ll1v = (s1 + t1) * 0.5f, ch1 = (s1 - t1) * 0.5f;
        float cv1 = (u1 + v1) * 0.5f, cd1 = (u1 - v1) * 0.5f;
        a_w2 += fminf(fabsf(ch0), THR2) + fminf(fabsf(cv0), THR2) + fminf(fabsf(cd0), THR2)
              + fminf(fabsf(ch1), THR2) + fminf(fabsf(cv1), THR2) + fminf(fabsf(cd1), THR2);
        ll2[i * 36 + 2 * j]     = ll0;
        ll2[i * 36 + 2 * j + 1] = ll1v;
    }
    __syncthreads();

    // ---- Haar level 3: 16x32 -> 8x16 details only (THR1) ----
    if (tid < 64) {
        int i = tid >> 3, j = tid & 7;
        float4 tp = ((const float4*)&ll2[(2 * i) * 36])[j];
        float4 bt = ((const float4*)&ll2[(2 * i + 1) * 36])[j];
        float s0 = tp.x + tp.y, t0 = bt.x + bt.y, u0 = tp.x - tp.y, v0 = bt.x - bt.y;
        float ch0 = (s0 - t0) * 0.5f, cv0 = (u0 + v0) * 0.5f, cd0 = (u0 - v0) * 0.5f;
        float s1 = tp.z + tp.w, t1 = bt.z + bt.w, u1 = tp.z - tp.w, v1 = bt.z - bt.w;
        float ch1 = (s1 - t1) * 0.5f, cv1 = (u1 + v1) * 0.5f, cd1 = (u1 - v1) * 0.5f;
        a_w1 += fminf(fabsf(ch0), THR1) + fminf(fabsf(cv0), THR1) + fminf(fabsf(cd0), THR1)
              + fminf(fabsf(ch1), THR1) + fminf(fabsf(cv1), THR1) + fminf(fabsf(cd1), THR1);
    }

    // ---- block reduce 6 partials, one double atomic each ----
    float vals[6] = {a_n2v, a_msk, a_w1, a_w2, a_w3, a_tv};
    int lane = tid & 31, warp = tid >> 5;
    #pragma unroll
    for (int k = 0; k < 6; k++) {
        float s = warp_sum(vals[k]);
        if (lane == 0) red[k][warp] = s;
    }
    __syncthreads();
    if (tid == 0) {
        #pragma unroll
        for (int k = 0; k < 6; k++) {
            float s = 0.f;
            #pragma unroll
            for (int w = 0; w < 8; w++) s += red[k][w];
            atomicAdd(&g_acc[k], (double)s);
        }
    }
}

__global__ void finalize(float* __restrict__ out) {
    double n2v = g_acc[0] / fmax(g_acc[1], 1.0);
    double wav = 1.0       * (g_acc[2] / (3.0 * B_ * 64.0  * 64.0))
               + (1.0/2.0) * (g_acc[3] / (3.0 * B_ * 128.0 * 128.0))
               + (1.0/3.0) * (g_acc[4] / (3.0 * B_ * 256.0 * 256.0));
    double tv  = g_acc[5] / ((double)B_ * 511.0 * 512.0);
    out[0] = (float)(1.0 * n2v + 0.2 * wav + 0.01 * tv);
}

extern "C" void kernel_launch(void* const* d_in, const int* in_sizes, int n_in,
                              void* d_out, int out_size) {
    const float* pred  = (const float*)d_in[0];
    const float* noisy = (const float*)d_in[1];
    const void*  mask  = d_in[2];
    float* out = (float*)d_out;

    init_acc<<<1, 32>>>();
    detect_mask_layout<<<64, 256>>>((const unsigned int*)mask);
    dim3 grid(W_ / TW, H_ / TH, B_);
    loss_kernel<<<grid, 256>>>(pred, noisy,
                               (const unsigned char*)mask,
                               (const unsigned int*)mask);
    finalize<<<1, 1>>>(out);
}

// round 5
// speedup vs baseline: 1.7692x; 1.0971x over previous
#include <cuda_runtime.h>
#include <cuda_bf16.h>
#include <math.h>

// Loss = 1.0*n2v + 0.2*wav + 0.01*tv over pred/noisy (64,1,512,512) f32, mask bool.
// Identity: |c - soft_threshold(c, thr)| == min(|c|, thr).
// Mask layout runtime-detected (1-byte bool vs 4-byte int/float; word!=0 covers both).
// Noisy loaded only for float4 groups with >=1 masked pixel (~8%).
// p4/n4 are pre-offset by img_off: index with IMAGE-LOCAL offsets only.

#define B_   64
#define H_   512
#define W_   512
#define TH   64
#define TW   128
#define SMS  132                       // smem row stride (floats); 132*4 % 16 == 0
#define NBLK ((W_/TW)*(H_/TH)*B_)      // 2048

#define THR1 (50.0f / 255.0f)
#define THR2 (25.0f / 255.0f)
#define THR3 (12.5f / 255.0f)

// per-block partials: [0]=n2v [1]=mask [2]=wav64 [3]=wav128 [4]=wav256 [5]=tv
__device__ float g_part[6][NBLK];
__device__ int   g_mask_is_byte;

// One block scans 64KB of mask words. Byte-packed bools (2% ones, ~1300 set bytes
// here) must yield words outside {0,1,0x3F800000}; int32/f32 encodings never do.
__global__ void detect_mask_layout(const unsigned int* __restrict__ mw) {
    int found = 0;
    for (int i = threadIdx.x; i < 16384; i += 256) {
        unsigned int w = mw[i];
        if (w != 0u && w != 1u && w != 0x3F800000u) found = 1;
    }
    int r = __syncthreads_or(found);
    if (threadIdx.x == 0) g_mask_is_byte = r ? 1 : 0;
}

__device__ __forceinline__ float warp_sum(float v) {
    #pragma unroll
    for (int o = 16; o > 0; o >>= 1) v += __shfl_down_sync(0xFFFFFFFFu, v, o);
    return v;
}

__device__ __forceinline__ float clipf(float x) {
    return fminf(fmaxf(x, 0.0f), 1.0f);
}

__global__ __launch_bounds__(256)
void loss_kernel(const float* __restrict__ pred,
                 const float* __restrict__ noisy,
                 const unsigned char* __restrict__ mask8,
                 const unsigned int* __restrict__ mask32) {
    __shared__ float sm [65 * SMS];
    __shared__ float ll1[32 * 68];
    __shared__ float ll2[16 * 36];
    __shared__ float red[6][8];

    const int tid = threadIdx.x;
    const int b   = blockIdx.z;
    const int r0  = blockIdx.y * TH;
    const int c0  = blockIdx.x * TW;
    const int bid = (blockIdx.z * gridDim.y + blockIdx.y) * gridDim.x + blockIdx.x;
    const size_t img_off = (size_t)b * H_ * W_;
    const float4* p4 = (const float4*)(pred  + img_off);
    const float4* n4 = (const float4*)(noisy + img_off);
    const int mask_is_byte = g_mask_is_byte;
    const bool last_row_tile = (r0 + TH == H_);
    const bool last_col_tile = (c0 + TW == W_);

    float a_n2v = 0.f, a_msk = 0.f, a_tv = 0.f;
    float a_w1 = 0.f, a_w2 = 0.f, a_w3 = 0.f;

    // ===== PHASE A (single GMEM latency window): pred->smem, mask, sparse noisy =====
    #pragma unroll
    for (int k = 0; k < TH * (TW / 4) / 256; k++) {
        int t = tid + k * 256;
        int lr = t >> 5, v = t & 31;
        float4 p = __ldg(&p4[(size_t)(r0 + lr) * (W_ / 4) + (c0 >> 2) + v]);
        p.x = clipf(p.x); p.y = clipf(p.y); p.z = clipf(p.z); p.w = clipf(p.w);
        ((float4*)&sm[lr * SMS])[v] = p;

        size_t loff = (size_t)(r0 + lr) * W_ + c0 + 4 * v;
        size_t pix  = img_off + loff;
        float m0, m1, m2, m3;
        bool any;
        if (mask_is_byte) {
            unsigned w = __ldg((const unsigned*)(mask8 + pix));
            any = (w != 0u);
            m0 = (w & 0x000000FFu) ? 1.f : 0.f;
            m1 = (w & 0x0000FF00u) ? 1.f : 0.f;
            m2 = (w & 0x00FF0000u) ? 1.f : 0.f;
            m3 = (w & 0xFF000000u) ? 1.f : 0.f;
        } else {
            uint4 w = __ldg((const uint4*)(mask32 + pix));
            any = (w.x | w.y | w.z | w.w) != 0u;
            m0 = w.x ? 1.f : 0.f; m1 = w.y ? 1.f : 0.f;
            m2 = w.z ? 1.f : 0.f; m3 = w.w ? 1.f : 0.f;
        }
        a_msk += (m0 + m1) + (m2 + m3);
        if (any) {
            float4 nv = __ldg(&n4[loff >> 2]);
            a_n2v += fabsf(p.x - nv.x) * m0 + fabsf(p.y - nv.y) * m1
                   + fabsf(p.z - nv.z) * m2 + fabsf(p.w - nv.w) * m3;
        }
    }
    // halo row (lr=64)
    if (tid < TW / 4) {
        float4 x = make_float4(0.f, 0.f, 0.f, 0.f);
        if (!last_row_tile) {
            x = __ldg(&p4[(size_t)(r0 + TH) * (W_ / 4) + (c0 >> 2) + tid]);
            x.x = clipf(x.x); x.y = clipf(x.y); x.z = clipf(x.z); x.w = clipf(x.w);
        }
        ((float4*)&sm[TH * SMS])[tid] = x;
    }
    // halo col (lc=128)
    if (tid >= 64 && tid < 128) {
        int lr = tid - 64;
        float x = 0.f;
        if (!last_col_tile)
            x = clipf(__ldg(&pred[img_off + (size_t)(r0 + lr) * W_ + c0 + TW]));
        sm[lr * SMS + TW] = x;
    }
    __syncthreads();

    // ===== PHASE B: TV (smem only) =====
    #pragma unroll
    for (int k = 0; k < TH * (TW / 4) / 256; k++) {
        int t = tid + k * 256;
        int lr = t >> 5, v = t & 31;
        float4 p = ((const float4*)&sm[lr * SMS])[v];
        float4 d = ((const float4*)&sm[(lr + 1) * SMS])[v];
        float  rt = sm[lr * SMS + 4 * v + 4];
        float hm = (last_col_tile && v == 31) ? 0.f : 1.f;
        float vm = (last_row_tile && lr == 63) ? 0.f : 1.f;
        a_tv += fabsf(p.y - p.x) + fabsf(p.z - p.y) + fabsf(p.w - p.z)
              + hm * fabsf(rt - p.w)
              + vm * (fabsf(d.x - p.x) + fabsf(d.y - p.y)
                    + fabsf(d.z - p.z) + fabsf(d.w - p.w));
    }

    // ===== Haar level 1: 64x128 -> 32x64 (THR3) =====
    #pragma unroll
    for (int t = tid; t < 32 * 32; t += 256) {
        int i = t >> 5, j = t & 31;
        float4 tp = ((const float4*)&sm[(2 * i) * SMS])[j];
        float4 bt = ((const float4*)&sm[(2 * i + 1) * SMS])[j];
        float s0 = tp.x + tp.y, t0 = bt.x + bt.y, u0 = tp.x - tp.y, v0 = bt.x - bt.y;
        float ll0 = (s0 + t0) * 0.5f, ch0 = (s0 - t0) * 0.5f;
        float cv0 = (u0 + v0) * 0.5f, cd0 = (u0 - v0) * 0.5f;
        float s1 = tp.z + tp.w, t1 = bt.z + bt.w, u1 = tp.z - tp.w, v1 = bt.z - bt.w;
        float ll1v = (s1 + t1) * 0.5f, ch1 = (s1 - t1) * 0.5f;
        float cv1 = (u1 + v1) * 0.5f, cd1 = (u1 - v1) * 0.5f;
        a_w3 += fminf(fabsf(ch0), THR3) + fminf(fabsf(cv0), THR3) + fminf(fabsf(cd0), THR3)
              + fminf(fabsf(ch1), THR3) + fminf(fabsf(cv1), THR3) + fminf(fabsf(cd1), THR3);
        ll1[i * 68 + 2 * j]     = ll0;
        ll1[i * 68 + 2 * j + 1] = ll1v;
    }
    __syncthreads();

    // ===== Haar level 2: 32x64 -> 16x32 (THR2) =====
    {
        int i = tid >> 4, j = tid & 15;
        float4 tp = ((const float4*)&ll1[(2 * i) * 68])[j];
        float4 bt = ((const float4*)&ll1[(2 * i + 1) * 68])[j];
        float s0 = tp.x + tp.y, t0 = bt.x + bt.y, u0 = tp.x - tp.y, v0 = bt.x - bt.y;
        float ll0 = (s0 + t0) * 0.5f, ch0 = (s0 - t0) * 0.5f;
        float cv0 = (u0 + v0) * 0.5f, cd0 = (u0 - v0) * 0.5f;
        float s1 = tp.z + tp.w, t1 = bt.z + bt.w, u1 = tp.z - tp.w, v1 = bt.z - bt.w;
        float ll1v = (s1 + t1) * 0.5f, ch1 = (s1 - t1) * 0.5f;
        float cv1 = (u1 + v1) * 0.5f, cd1 = (u1 - v1) * 0.5f;
        a_w2 += fminf(fabsf(ch0), THR2) + fminf(fabsf(cv0), THR2) + fminf(fabsf(cd0), THR2)
              + fminf(fabsf(ch1), THR2) + fminf(fabsf(cv1), THR2) + fminf(fabsf(cd1), THR2);
        ll2[i * 36 + 2 * j]     = ll0;
        ll2[i * 36 + 2 * j + 1] = ll1v;
    }
    __syncthreads();

    // ===== Haar level 3: 16x32 -> 8x16 details (THR1) =====
    if (tid < 64) {
        int i = tid >> 3, j = tid & 7;
        float4 tp = ((const float4*)&ll2[(2 * i) * 36])[j];
        float4 bt = ((const float4*)&ll2[(2 * i + 1) * 36])[j];
        float s0 = tp.x + tp.y, t0 = bt.x + bt.y, u0 = tp.x - tp.y, v0 = bt.x - bt.y;
        float ch0 = (s0 - t0) * 0.5f, cv0 = (u0 + v0) * 0.5f, cd0 = (u0 - v0) * 0.5f;
        float s1 = tp.z + tp.w, t1 = bt.z + bt.w, u1 = tp.z - tp.w, v1 = bt.z - bt.w;
        float ch1 = (s1 - t1) * 0.5f, cv1 = (u1 + v1) * 0.5f, cd1 = (u1 - v1) * 0.5f;
        a_w1 += fminf(fabsf(ch0), THR1) + fminf(fabsf(cv0), THR1) + fminf(fabsf(cd0), THR1)
              + fminf(fabsf(ch1), THR1) + fminf(fabsf(cv1), THR1) + fminf(fabsf(cd1), THR1);
    }

    // ===== block reduce, write partials (no atomics, no init) =====
    float vals[6] = {a_n2v, a_msk, a_w1, a_w2, a_w3, a_tv};
    int lane = tid & 31, warp = tid >> 5;
    #pragma unroll
    for (int k = 0; k < 6; k++) {
        float s = warp_sum(vals[k]);
        if (lane == 0) red[k][warp] = s;
    }
    __syncthreads();
    if (tid == 0) {
        #pragma unroll
        for (int k = 0; k < 6; k++) {
            float s = 0.f;
            #pragma unroll
            for (int w = 0; w < 8; w++) s += red[k][w];
            g_part[k][bid] = s;
        }
    }
}

__global__ __launch_bounds__(256)
void finalize(float* __restrict__ out) {
    __shared__ double sred[6][8];
    const int tid = threadIdx.x, lane = tid & 31, warp = tid >> 5;
    double acc[6] = {0, 0, 0, 0, 0, 0};
    for (int i = tid; i < NBLK; i += 256) {
        #pragma unroll
        for (int k = 0; k < 6; k++) acc[k] += (double)g_part[k][i];
    }
    #pragma unroll
    for (int k = 0; k < 6; k++) {
        #pragma unroll
        for (int o = 16; o > 0; o >>= 1)
            acc[k] += __shfl_down_sync(0xFFFFFFFFu, acc[k], o);
        if (lane == 0) sred[k][warp] = acc[k];
    }
    __syncthreads();
    if (tid == 0) {
        double t[6];
        #pragma unroll
        for (int k = 0; k < 6; k++) {
            double s = 0.0;
            #pragma unroll
            for (int w = 0; w < 8; w++) s += sred[k][w];
            t[k] = s;
        }
        double n2v = t[0] / fmax(t[1], 1.0);
        double wav = 1.0       * (t[2] / (3.0 * B_ * 64.0  * 64.0))
                   + (1.0/2.0) * (t[3] / (3.0 * B_ * 128.0 * 128.0))
                   + (1.0/3.0) * (t[4] / (3.0 * B_ * 256.0 * 256.0));
        double tv  = t[5] / ((double)B_ * 511.0 * 512.0);
        out[0] = (float)(1.0 * n2v + 0.2 * wav + 0.01 * tv);
    }
}

extern "C" void kernel_launch(void* const* d_in, const int* in_sizes, int n_in,
                              void* d_out, int out_size) {
    const float* pred  = (const float*)d_in[0];
    const float* noisy = (const float*)d_in[1];
    const void*  mask  = d_in[2];
    float* out = (float*)d_out;

    detect_mask_layout<<<1, 256>>>((const unsigned int*)mask);
    dim3 grid(W_ / TW, H_ / TH, B_);
    loss_kernel<<<grid, 256>>>(pred, noisy,
                               (const unsigned char*)mask,
                               (const unsigned int*)mask);
    finalize<<<1, 256>>>(out);
}

// round 6
// speedup vs baseline: 1.9720x; 1.1146x over previous
#include <cuda_runtime.h>
#include <cuda_bf16.h>
#include <math.h>

// Loss = 1.0*n2v + 0.2*wav + 0.01*tv over pred/noisy (64,1,512,512) f32, mask bool.
// Identity: |c - soft_threshold(c, thr)| == min(|c|, thr).
// Single-kernel design: per-block mask-layout probe (first 2KB, L2-resident),
// fused last-block finalize (threadfence + counter), register-staged DWT level 1.
// p4/n4 are pre-offset by img_off: index with IMAGE-LOCAL offsets only.

#define B_   64
#define H_   512
#define W_   512
#define TH   64
#define TW   128
#define SMS  132                       // smem row stride (floats); 132*4 % 16 == 0
#define NBLK ((W_/TW)*(H_/TH)*B_)      // 2048

#define THR1 (50.0f / 255.0f)
#define THR2 (25.0f / 255.0f)
#define THR3 (12.5f / 255.0f)

// per-block partials: [0]=n2v [1]=mask [2]=wav64 [3]=wav128 [4]=wav256 [5]=tv
__device__ float    g_part[6][NBLK];
__device__ unsigned g_done;            // zero-init; last block resets it each replay

__device__ __forceinline__ float warp_sumf(float v) {
    #pragma unroll
    for (int o = 16; o > 0; o >>= 1) v += __shfl_down_sync(0xFFFFFFFFu, v, o);
    return v;
}

__device__ __forceinline__ float clipf(float x) {
    return fminf(fmaxf(x, 0.0f), 1.0f);
}

__global__ __launch_bounds__(256)
void loss_kernel(const float* __restrict__ pred,
                 const float* __restrict__ noisy,
                 const unsigned char* __restrict__ mask8,
                 const unsigned int* __restrict__ mask32,
                 float* __restrict__ out) {
    __shared__ float sm [65 * SMS];    // clipped tile + halo; later overlaid by L1 LL (32x68)
    __shared__ float ll2[16 * 36];
    __shared__ float red[6][8];
    __shared__ bool  amLast;

    const int tid = threadIdx.x;
    const int b   = blockIdx.z;
    const int r0  = blockIdx.y * TH;
    const int c0  = blockIdx.x * TW;
    const int bid = (blockIdx.z * gridDim.y + blockIdx.y) * gridDim.x + blockIdx.x;
    const size_t img_off = (size_t)b * H_ * W_;
    const float4* p4 = (const float4*)(pred  + img_off);
    const float4* n4 = (const float4*)(noisy + img_off);
    const bool last_row_tile = (r0 + TH == H_);
    const bool last_col_tile = (c0 + TW == W_);

    // ---- mask layout probe: first 512 words (2KB, same for all blocks => L2 hit).
    // byte-packed bools yield words outside {0,1,0x3F800000}; int32/f32 never do.
    unsigned pw0 = mask32[tid], pw1 = mask32[tid + 256];
    int bad = ((pw0 != 0u && pw0 != 1u && pw0 != 0x3F800000u) ||
               (pw1 != 0u && pw1 != 1u && pw1 != 0x3F800000u)) ? 1 : 0;
    const int mask_is_byte = __syncthreads_or(bad);

    float a_n2v = 0.f, a_msk = 0.f, a_tv = 0.f;
    float a_w1 = 0.f, a_w2 = 0.f, a_w3 = 0.f;

    // ===== PHASE A (one GMEM window): pred->smem, mask, sparse noisy =====
    #pragma unroll
    for (int k = 0; k < TH * (TW / 4) / 256; k++) {
        int t = tid + k * 256;
        int lr = t >> 5, v = t & 31;
        float4 p = __ldg(&p4[(size_t)(r0 + lr) * (W_ / 4) + (c0 >> 2) + v]);
        p.x = clipf(p.x); p.y = clipf(p.y); p.z = clipf(p.z); p.w = clipf(p.w);
        ((float4*)&sm[lr * SMS])[v] = p;

        size_t loff = (size_t)(r0 + lr) * W_ + c0 + 4 * v;
        size_t pix  = img_off + loff;
        float m0, m1, m2, m3;
        bool any;
        if (mask_is_byte) {
            unsigned w = __ldg((const unsigned*)(mask8 + pix));
            any = (w != 0u);
            m0 = (w & 0x000000FFu) ? 1.f : 0.f;
            m1 = (w & 0x0000FF00u) ? 1.f : 0.f;
            m2 = (w & 0x00FF0000u) ? 1.f : 0.f;
            m3 = (w & 0xFF000000u) ? 1.f : 0.f;
        } else {
            uint4 w = __ldg((const uint4*)(mask32 + pix));
            any = (w.x | w.y | w.z | w.w) != 0u;
            m0 = w.x ? 1.f : 0.f; m1 = w.y ? 1.f : 0.f;
            m2 = w.z ? 1.f : 0.f; m3 = w.w ? 1.f : 0.f;
        }
        a_msk += (m0 + m1) + (m2 + m3);
        if (any) {
            float4 nv = __ldg(&n4[loff >> 2]);
            a_n2v += fabsf(p.x - nv.x) * m0 + fabsf(p.y - nv.y) * m1
                   + fabsf(p.z - nv.z) * m2 + fabsf(p.w - nv.w) * m3;
        }
    }
    // halo row (lr=64)
    if (tid < TW / 4) {
        float4 x = make_float4(0.f, 0.f, 0.f, 0.f);
        if (!last_row_tile) {
            x = __ldg(&p4[(size_t)(r0 + TH) * (W_ / 4) + (c0 >> 2) + tid]);
            x.x = clipf(x.x); x.y = clipf(x.y); x.z = clipf(x.z); x.w = clipf(x.w);
        }
        ((float4*)&sm[TH * SMS])[tid] = x;
    }
    // halo col (lc=128)
    if (tid >= 64 && tid < 128) {
        int lr = tid - 64;
        float x = 0.f;
        if (!last_col_tile)
            x = clipf(__ldg(&pred[img_off + (size_t)(r0 + lr) * W_ + c0 + TW]));
        sm[lr * SMS + TW] = x;
    }
    __syncthreads();

    // ===== PHASE B: TV (smem only) + Haar level 1 into registers =====
    float llr[4][2];   // level-1 LL coeffs staged in registers

    #pragma unroll
    for (int k = 0; k < TH * (TW / 4) / 256; k++) {
        int t = tid + k * 256;
        int lr = t >> 5, v = t & 31;
        float4 p = ((const float4*)&sm[lr * SMS])[v];
        float4 d = ((const float4*)&sm[(lr + 1) * SMS])[v];
        float  rt = sm[lr * SMS + 4 * v + 4];
        float hm = (last_col_tile && v == 31) ? 0.f : 1.f;
        float vm = (last_row_tile && lr == 63) ? 0.f : 1.f;
        a_tv += fabsf(p.y - p.x) + fabsf(p.z - p.y) + fabsf(p.w - p.z)
              + hm * fabsf(rt - p.w)
              + vm * (fabsf(d.x - p.x) + fabsf(d.y - p.y)
                    + fabsf(d.z - p.z) + fabsf(d.w - p.w));
    }

    #pragma unroll
    for (int k = 0; k < 4; k++) {                 // 32x32 items, 2 outputs each
        int t = tid + k * 256;
        int i = t >> 5, j = t & 31;
        float4 tp = ((const float4*)&sm[(2 * i) * SMS])[j];
        float4 bt = ((const float4*)&sm[(2 * i + 1) * SMS])[j];
        float s0 = tp.x + tp.y, t0 = bt.x + bt.y, u0 = tp.x - tp.y, v0 = bt.x - bt.y;
        float ch0 = (s0 - t0) * 0.5f, cv0 = (u0 + v0) * 0.5f, cd0 = (u0 - v0) * 0.5f;
        float s1 = tp.z + tp.w, t1 = bt.z + bt.w, u1 = tp.z - tp.w, v1 = bt.z - bt.w;
        float ch1 = (s1 - t1) * 0.5f, cv1 = (u1 + v1) * 0.5f, cd1 = (u1 - v1) * 0.5f;
        a_w3 += fminf(fabsf(ch0), THR3) + fminf(fabsf(cv0), THR3) + fminf(fabsf(cd0), THR3)
              + fminf(fabsf(ch1), THR3) + fminf(fabsf(cv1), THR3) + fminf(fabsf(cd1), THR3);
        llr[k][0] = (s0 + t0) * 0.5f;
        llr[k][1] = (s1 + t1) * 0.5f;
    }
    __syncthreads();          // all sm reads done; overlay L1 LL into sm (32x68)

    #pragma unroll
    for (int k = 0; k < 4; k++) {
        int t = tid + k * 256;
        int i = t >> 5, j = t & 31;
        sm[i * 68 + 2 * j]     = llr[k][0];
        sm[i * 68 + 2 * j + 1] = llr[k][1];
    }
    __syncthreads();

    // ===== Haar level 2: 32x64 -> 16x32 (THR2) =====
    {
        int i = tid >> 4, j = tid & 15;
        float4 tp = ((const float4*)&sm[(2 * i) * 68])[j];
        float4 bt = ((const float4*)&sm[(2 * i + 1) * 68])[j];
        float s0 = tp.x + tp.y, t0 = bt.x + bt.y, u0 = tp.x - tp.y, v0 = bt.x - bt.y;
        float ch0 = (s0 - t0) * 0.5f, cv0 = (u0 + v0) * 0.5f, cd0 = (u0 - v0) * 0.5f;
        float s1 = tp.z + tp.w, t1 = bt.z + bt.w, u1 = tp.z - tp.w, v1 = bt.z - bt.w;
        float ch1 = (s1 - t1) * 0.5f, cv1 = (u1 + v1) * 0.5f, cd1 = (u1 - v1) * 0.5f;
        a_w2 += fminf(fabsf(ch0), THR2) + fminf(fabsf(cv0), THR2) + fminf(fabsf(cd0), THR2)
              + fminf(fabsf(ch1), THR2) + fminf(fabsf(cv1), THR2) + fminf(fabsf(cd1), THR2);
        ll2[i * 36 + 2 * j]     = (s0 + t0) * 0.5f;
        ll2[i * 36 + 2 * j + 1] = (s1 + t1) * 0.5f;
    }
    __syncthreads();

    // ===== Haar level 3: 16x32 -> 8x16 details (THR1) =====
    if (tid < 64) {
        int i = tid >> 3, j = tid & 7;
        float4 tp = ((const float4*)&ll2[(2 * i) * 36])[j];
        float4 bt = ((const float4*)&ll2[(2 * i + 1) * 36])[j];
        float s0 = tp.x + tp.y, t0 = bt.x + bt.y, u0 = tp.x - tp.y, v0 = bt.x - bt.y;
        float ch0 = (s0 - t0) * 0.5f, cv0 = (u0 + v0) * 0.5f, cd0 = (u0 - v0) * 0.5f;
        float s1 = tp.z + tp.w, t1 = bt.z + bt.w, u1 = tp.z - tp.w, v1 = bt.z - bt.w;
        float ch1 = (s1 - t1) * 0.5f, cv1 = (u1 + v1) * 0.5f, cd1 = (u1 - v1) * 0.5f;
        a_w1 += fminf(fabsf(ch0), THR1) + fminf(fabsf(cv0), THR1) + fminf(fabsf(cd0), THR1)
              + fminf(fabsf(ch1), THR1) + fminf(fabsf(cv1), THR1) + fminf(fabsf(cd1), THR1);
    }

    // ===== block reduce, write partials =====
    float vals[6] = {a_n2v, a_msk, a_w1, a_w2, a_w3, a_tv};
    int lane = tid & 31, warp = tid >> 5;
    #pragma unroll
    for (int k = 0; k < 6; k++) {
        float s = warp_sumf(vals[k]);
        if (lane == 0) red[k][warp] = s;
    }
    __syncthreads();
    if (tid == 0) {
        #pragma unroll
        for (int k = 0; k < 6; k++) {
            float s = 0.f;
            #pragma unroll
            for (int w = 0; w < 8; w++) s += red[k][w];
            g_part[k][bid] = s;
        }
        __threadfence();
        unsigned prev = atomicAdd(&g_done, 1u);
        amLast = (prev == NBLK - 1);
    }
    __syncthreads();

    // ===== last block: fused finalize =====
    if (amLast) {
        __shared__ double sred[6][8];
        double acc[6] = {0, 0, 0, 0, 0, 0};
        for (int i = tid; i < NBLK; i += 256) {
            #pragma unroll
            for (int k = 0; k < 6; k++)
                acc[k] += (double)((volatile float*)g_part[k])[i];
        }
        #pragma unroll
        for (int k = 0; k < 6; k++) {
            #pragma unroll
            for (int o = 16; o > 0; o >>= 1)
                acc[k] += __shfl_down_sync(0xFFFFFFFFu, acc[k], o);
            if (lane == 0) sred[k][warp] = acc[k];
        }
        __syncthreads();
        if (tid == 0) {
            double t[6];
            #pragma unroll
            for (int k = 0; k < 6; k++) {
                double s = 0.0;
                #pragma unroll
                for (int w = 0; w < 8; w++) s += sred[k][w];
                t[k] = s;
            }
            double n2v = t[0] / fmax(t[1], 1.0);
            double wav = 1.0       * (t[2] / (3.0 * B_ * 64.0  * 64.0))
                       + (1.0/2.0) * (t[3] / (3.0 * B_ * 128.0 * 128.0))
                       + (1.0/3.0) * (t[4] / (3.0 * B_ * 256.0 * 256.0));
            double tv  = t[5] / ((double)B_ * 511.0 * 512.0);
            out[0] = (float)(1.0 * n2v + 0.2 * wav + 0.01 * tv);
            g_done = 0;   // reset for next graph replay
        }
    }
}

extern "C" void kernel_launch(void* const* d_in, const int* in_sizes, int n_in,
                              void* d_out, int out_size) {
    const float* pred  = (const float*)d_in[0];
    const float* noisy = (const float*)d_in[1];
    const void*  mask  = d_in[2];
    float* out = (float*)d_out;

    dim3 grid(W_ / TW, H_ / TH, B_);
    loss_kernel<<<grid, 256>>>(pred, noisy,
                               (const unsigned char*)mask,
                               (const unsigned int*)mask,
                               out);
}